// round 8
// baseline (speedup 1.0000x reference)
#include <cuda_runtime.h>

#define LEADS 42
#define HID   10
#define BT    64          // batch rows per block tile
#define RG    2           // row groups of 32 (BT/32)
#define THREADS 256
#define NWARP (THREADS/32)
#define ROW2  43          // padded float2 per b-row in shared (42 -> 43)

// tanh(m/2) = 0.5*m*Q(m^2), Q(v) = 1 + QC1*v + QC2*v^2 + QC3*v^3 + QC4*v^4
// (rescaled from tanh(c)/c fit on |c|<=1, max abs err ~5e-5)
#define QC1 (-0.08332301f)
#define QC2 ( 0.0082748175f)
#define QC3 (-0.000761302f)
#define QC4 ( 4.3798828e-5f)

// packed weights in global scratch (device-global arrays are allowed scratch)
__device__ float4 g_w[LEADS * HID * 3];
__device__ float2 g_bfc[LEADS];

__device__ __forceinline__ float tanh_approx(float x) {
    float y;
    asm("tanh.approx.f32 %0, %1;" : "=f"(y) : "f"(x));
    return y;
}

// ---- pre-kernel: pack weights once per launch (1 block, trivial) ----
__global__ void pack_weights_kernel(const float* __restrict__ W_ih,
                                    const float* __restrict__ b_ih,
                                    const float* __restrict__ b_hh,
                                    const float* __restrict__ W_fc,
                                    const float* __restrict__ b_fc)
{
    int u = threadIdx.x;
    if (u < LEADS * HID) {
        int t = u / HID;
        int h = u - t * HID;
        const float* Wt = W_ih + (long)t * 40 * 2;
        float wi0 = Wt[(0 * HID + h) * 2 + 0];
        float wi1 = Wt[(0 * HID + h) * 2 + 1];
        float wg0 = Wt[(2 * HID + h) * 2 + 0];
        float wg1 = Wt[(2 * HID + h) * 2 + 1];
        float wo0 = Wt[(3 * HID + h) * 2 + 0];
        float wo1 = Wt[(3 * HID + h) * 2 + 1];
        float bi  = b_ih[t * 40 + 0 * HID + h] + b_hh[t * 40 + 0 * HID + h];
        float bg  = b_ih[t * 40 + 2 * HID + h] + b_hh[t * 40 + 2 * HID + h];
        float bo  = b_ih[t * 40 + 3 * HID + h] + b_hh[t * 40 + 3 * HID + h];
        // [.5wi0,.5wi1,.5bi, wg0 | wg1,bg,.5wo0,.5wo1 | .5bo,.25wf0,.25wf1, 0]
        g_w[u * 3 + 0] = make_float4(0.5f * wi0, 0.5f * wi1, 0.5f * bi, wg0);
        g_w[u * 3 + 1] = make_float4(wg1, bg, 0.5f * wo0, 0.5f * wo1);
        g_w[u * 3 + 2] = make_float4(0.5f * bo,
                                     0.25f * W_fc[((long)t * 2 + 0) * HID + h],
                                     0.25f * W_fc[((long)t * 2 + 1) * HID + h],
                                     0.0f);
    }
    if (u < LEADS) {
        g_bfc[u] = make_float2(b_fc[u * 2 + 0], b_fc[u * 2 + 1]);
    }
}

__global__ __launch_bounds__(THREADS, 6)
void perlead_lstm_kernel(const float* __restrict__ x,
                         float* __restrict__ y)
{
    __shared__ float2 sx2[BT * ROW2];     // x tile, overwritten with y in place

    const int tid  = threadIdx.x;
    const int lane = tid & 31;
    const int warp = tid >> 5;
    const long base2 = (long)blockIdx.x * (BT * LEADS);   // float2 units

    // ---- stage x tile (coalesced float2 global read) ----
    const float2* xg = reinterpret_cast<const float2*>(x) + base2;
    #pragma unroll 1
    for (int idx = tid; idx < BT * LEADS; idx += THREADS) {
        int bl = idx / LEADS;
        int j  = idx - bl * LEADS;
        sx2[bl * ROW2 + j] = xg[idx];
    }
    __syncthreads();

    // ---- compute: warp-uniform t; weights via uniform-address LDG (L1-hot) ----
    for (int t = warp; t < LEADS; t += NWARP) {
        float2 xv[RG];
        float  y0[RG], y1[RG];
        float2 bfc = __ldg(&g_bfc[t]);
        #pragma unroll
        for (int r = 0; r < RG; r++) {
            xv[r] = sx2[(r * 32 + lane) * ROW2 + t];
            y0[r] = bfc.x;
            y1[r] = bfc.y;
        }
        const float4* wt = g_w + t * (HID * 3);
        #pragma unroll
        for (int h = 0; h < HID; h++) {
            float4 a = __ldg(wt + h * 3 + 0);
            float4 b = __ldg(wt + h * 3 + 1);
            float4 c = __ldg(wt + h * 3 + 2);
            #pragma unroll
            for (int r = 0; r < RG; r++) {
                float iv = fmaf(a.x, xv[r].x, fmaf(a.y, xv[r].y, a.z));  // i/2
                float gv = fmaf(a.w, xv[r].x, fmaf(b.x, xv[r].y, b.y));  // g
                float ov = fmaf(b.z, xv[r].x, fmaf(b.w, xv[r].y, c.x));  // o/2
                float Ti = tanh_approx(iv);                               // tanh(i/2)
                float Tg = tanh_approx(gv);                               // tanh(g)
                float To = tanh_approx(ov);                               // tanh(o/2)
                float m  = fmaf(Ti, Tg, Tg);                              // 2c
                float v  = m * m;
                float q  = fmaf(fmaf(fmaf(QC4, v, QC3), v, QC2), v, QC1);
                float Qv = fmaf(v, q, 1.0f);
                float s  = m * Qv;                                        // 2*tanh(c)
                float t2 = fmaf(To, s, s);                                // 4*h
                y0[r] = fmaf(c.y, t2, y0[r]);                             // wf' = wf/4
                y1[r] = fmaf(c.z, t2, y1[r]);
            }
        }
        #pragma unroll
        for (int r = 0; r < RG; r++) {
            sx2[(r * 32 + lane) * ROW2 + t] = make_float2(y0[r], y1[r]);
        }
    }

    __syncthreads();

    // ---- write y tile (coalesced float2 global write) ----
    float2* yg = reinterpret_cast<float2*>(y) + base2;
    #pragma unroll 1
    for (int idx = tid; idx < BT * LEADS; idx += THREADS) {
        int bl = idx / LEADS;
        int j  = idx - bl * LEADS;
        yg[idx] = sx2[bl * ROW2 + j];
    }
}

extern "C" void kernel_launch(void* const* d_in, const int* in_sizes, int n_in,
                              void* d_out, int out_size) {
    const float* x    = (const float*)d_in[0];
    const float* W_ih = (const float*)d_in[1];
    const float* b_ih = (const float*)d_in[2];
    const float* b_hh = (const float*)d_in[3];
    const float* W_fc = (const float*)d_in[4];
    const float* b_fc = (const float*)d_in[5];
    float* y = (float*)d_out;

    pack_weights_kernel<<<1, 512>>>(W_ih, b_ih, b_hh, W_fc, b_fc);

    int B = in_sizes[0] / (LEADS * 2);   // 131072
    int blocks = B / BT;                 // 2048
    perlead_lstm_kernel<<<blocks, THREADS>>>(x, y);
}

// round 9
// speedup vs baseline: 1.0353x; 1.0353x over previous
#include <cuda_runtime.h>
#include <cuda_fp16.h>

#define LEADS 42
#define HID   10
#define BT    64          // batch rows per block tile
#define RG    2           // row groups of 32 (BT/32)
#define THREADS 256
#define NWARP (THREADS/32)
#define ROW2  43          // padded float2 per b-row in shared (42 -> 43)

// tanh(m/2) = 0.5*m*Q(m^2), Q(v) = 1 + QC1*v + QC2*v^2 + QC3*v^3 + QC4*v^4
// (rescaled from tanh(c)/c fit on |c|<=1, max abs err ~5e-5)
#define QC1 (-0.08332301f)
#define QC2 ( 0.0082748175f)
#define QC3 (-0.000761302f)
#define QC4 ( 4.3798828e-5f)

__device__ __forceinline__ float tanh_approx(float x) {
    float y;
    asm("tanh.approx.f32 %0, %1;" : "=f"(y) : "f"(x));
    return y;
}

// two tanhs in one MUFU op: returns {tanh(a), tanh(b)} computed in f16
__device__ __forceinline__ float2 tanh2_f16(float a, float b) {
    __half2 hv = __floats2half2_rn(a, b);     // x=a (lo), y=b (hi)
    unsigned int u = *reinterpret_cast<unsigned int*>(&hv);
    unsigned int r;
    asm("tanh.approx.f16x2 %0, %1;" : "=r"(r) : "r"(u));
    __half2 hr = *reinterpret_cast<__half2*>(&r);
    return __half22float2(hr);                // {tanh(a), tanh(b)}
}

extern __shared__ float smem_dyn[];

__global__ __launch_bounds__(THREADS)
void perlead_lstm_kernel(const float* __restrict__ x,
                         const float* __restrict__ W_ih,
                         const float* __restrict__ b_ih,
                         const float* __restrict__ b_hh,
                         const float* __restrict__ W_fc,
                         const float* __restrict__ b_fc,
                         float* __restrict__ y)
{
    // dynamic smem layout:
    //   sx2  : BT * ROW2 float2          (x tile, overwritten with y in place)
    //   sw4  : LEADS*HID*3 float4        (packed weights)
    //   sbfc : LEADS float2              (fc bias)
    float2* sx2  = reinterpret_cast<float2*>(smem_dyn);
    float4* sw4  = reinterpret_cast<float4*>(smem_dyn + BT * ROW2 * 2);
    float2* sbfc = reinterpret_cast<float2*>(smem_dyn + BT * ROW2 * 2 + LEADS * HID * 12);
    float*  swf  = reinterpret_cast<float*>(sw4);

    const int tid  = threadIdx.x;
    const int lane = tid & 31;
    const int warp = tid >> 5;
    const long base2 = (long)blockIdx.x * (BT * LEADS);   // float2 units

    // ---- stage x tile (coalesced float2 global read) ----
    const float2* xg = reinterpret_cast<const float2*>(x) + base2;
    #pragma unroll 1
    for (int idx = tid; idx < BT * LEADS; idx += THREADS) {
        int bl = idx / LEADS;
        int j  = idx - bl * LEADS;
        sx2[bl * ROW2 + j] = xg[idx];
    }

    // ---- pack weights into shared ----
    // per (t,h) 12 floats:
    // [.5wi0,.5wi1,.5bi, wg0,wg1,bg, .5wo0,.5wo1,.5bo, .25wf0,.25wf1, pad]
    for (int u = tid; u < LEADS * HID; u += THREADS) {
        int t = u / HID;
        int h = u - t * HID;
        const float* Wt = W_ih + (long)t * 40 * 2;
        float wi0 = Wt[(0 * HID + h) * 2 + 0];
        float wi1 = Wt[(0 * HID + h) * 2 + 1];
        float wg0 = Wt[(2 * HID + h) * 2 + 0];
        float wg1 = Wt[(2 * HID + h) * 2 + 1];
        float wo0 = Wt[(3 * HID + h) * 2 + 0];
        float wo1 = Wt[(3 * HID + h) * 2 + 1];
        float bi  = b_ih[t * 40 + 0 * HID + h] + b_hh[t * 40 + 0 * HID + h];
        float bg  = b_ih[t * 40 + 2 * HID + h] + b_hh[t * 40 + 2 * HID + h];
        float bo  = b_ih[t * 40 + 3 * HID + h] + b_hh[t * 40 + 3 * HID + h];
        float* d = swf + u * 12;
        d[0]  = 0.5f * wi0;   d[1]  = 0.5f * wi1;   d[2]  = 0.5f * bi;
        d[3]  = wg0;          d[4]  = wg1;          d[5]  = bg;
        d[6]  = 0.5f * wo0;   d[7]  = 0.5f * wo1;   d[8]  = 0.5f * bo;
        d[9]  = 0.25f * W_fc[((long)t * 2 + 0) * HID + h];
        d[10] = 0.25f * W_fc[((long)t * 2 + 1) * HID + h];
        d[11] = 0.0f;
    }
    if (tid < LEADS) {
        sbfc[tid] = make_float2(b_fc[tid * 2 + 0], b_fc[tid * 2 + 1]);
    }

    __syncthreads();

    // ---- compute: warp-uniform t; each weight load serves RG*32 rows ----
    for (int t = warp; t < LEADS; t += NWARP) {
        float2 xv[RG];
        float  y0[RG], y1[RG];
        float2 bfc = sbfc[t];
        #pragma unroll
        for (int r = 0; r < RG; r++) {
            xv[r] = sx2[(r * 32 + lane) * ROW2 + t];
            y0[r] = bfc.x;
            y1[r] = bfc.y;
        }
        const float4* wt = sw4 + t * HID * 3;
        #pragma unroll
        for (int h = 0; h < HID; h++) {
            float4 a = wt[h * 3 + 0];
            float4 b = wt[h * 3 + 1];
            float4 c = wt[h * 3 + 2];
            #pragma unroll
            for (int r = 0; r < RG; r++) {
                float iv = fmaf(a.x, xv[r].x, fmaf(a.y, xv[r].y, a.z));  // i/2
                float gv = fmaf(a.w, xv[r].x, fmaf(b.x, xv[r].y, b.y));  // g
                float ov = fmaf(b.z, xv[r].x, fmaf(b.w, xv[r].y, c.x));  // o/2
                float2 Tio = tanh2_f16(iv, ov);                           // {tanh(i/2), tanh(o/2)} via 1 MUFU
                float Tg = tanh_approx(gv);                               // tanh(g) in f32
                float Ti = Tio.x;
                float To = Tio.y;
                float m  = fmaf(Ti, Tg, Tg);                              // 2c = (Ti+1)*Tg
                float v  = m * m;
                float q  = fmaf(fmaf(fmaf(QC4, v, QC3), v, QC2), v, QC1);
                float Qv = fmaf(v, q, 1.0f);
                float s  = m * Qv;                                        // 2*tanh(c)
                float t2 = fmaf(To, s, s);                                // 4*h
                y0[r] = fmaf(c.y, t2, y0[r]);                             // wf' = wf/4
                y1[r] = fmaf(c.z, t2, y1[r]);
            }
        }
        #pragma unroll
        for (int r = 0; r < RG; r++) {
            sx2[(r * 32 + lane) * ROW2 + t] = make_float2(y0[r], y1[r]);
        }
    }

    __syncthreads();

    // ---- write y tile (coalesced float2 global write) ----
    float2* yg = reinterpret_cast<float2*>(y) + base2;
    #pragma unroll 1
    for (int idx = tid; idx < BT * LEADS; idx += THREADS) {
        int bl = idx / LEADS;
        int j  = idx - bl * LEADS;
        yg[idx] = sx2[bl * ROW2 + j];
    }
}

extern "C" void kernel_launch(void* const* d_in, const int* in_sizes, int n_in,
                              void* d_out, int out_size) {
    const float* x    = (const float*)d_in[0];
    const float* W_ih = (const float*)d_in[1];
    const float* b_ih = (const float*)d_in[2];
    const float* b_hh = (const float*)d_in[3];
    const float* W_fc = (const float*)d_in[4];
    const float* b_fc = (const float*)d_in[5];
    float* y = (float*)d_out;

    const int smem_bytes = BT * ROW2 * 8 + LEADS * HID * 48 + LEADS * 8;
    static bool attr_set = false;
    if (!attr_set) {
        cudaFuncSetAttribute(perlead_lstm_kernel,
                             cudaFuncAttributeMaxDynamicSharedMemorySize, smem_bytes);
        attr_set = true;
    }

    int B = in_sizes[0] / (LEADS * 2);   // 131072
    int blocks = B / BT;                 // 2048
    perlead_lstm_kernel<<<blocks, THREADS, smem_bytes>>>(x, W_ih, b_ih, b_hh, W_fc, b_fc, y);
}

// round 11
// speedup vs baseline: 1.1468x; 1.1077x over previous
#include <cuda_runtime.h>

#define LEADS 42
#define HID   10
#define HP    (HID/2)     // h-pairs
#define BT    64          // batch rows per block tile
#define RG    2           // row groups of 32 (BT/32)
#define THREADS 256
#define NWARP (THREADS/32)
#define ROW2  43          // padded float2 per b-row in shared (42 -> 43)

// tanh(m/2) = 0.5*m*Q(m^2), Q(v) = 1 + QC1*v + QC2*v^2 + QC3*v^3 + QC4*v^4
#define QC1 (-0.08332301f)
#define QC2 ( 0.0082748175f)
#define QC3 (-0.000761302f)
#define QC4 ( 4.3798828e-5f)

typedef unsigned long long u64;

__device__ __forceinline__ float tanh_approx(float x) {
    float y;
    asm("tanh.approx.f32 %0, %1;" : "=f"(y) : "f"(x));
    return y;
}
__device__ __forceinline__ u64 pk(float lo, float hi) {
    u64 r; asm("mov.b64 %0, {%1, %2};" : "=l"(r) : "f"(lo), "f"(hi)); return r;
}
__device__ __forceinline__ void upk(float& lo, float& hi, u64 v) {
    asm("mov.b64 {%0, %1}, %2;" : "=f"(lo), "=f"(hi) : "l"(v));
}
__device__ __forceinline__ u64 fma2(u64 a, u64 b, u64 c) {
    u64 d; asm("fma.rn.f32x2 %0, %1, %2, %3;" : "=l"(d) : "l"(a), "l"(b), "l"(c)); return d;
}
__device__ __forceinline__ u64 mul2(u64 a, u64 b) {
    u64 d; asm("mul.rn.f32x2 %0, %1, %2;" : "=l"(d) : "l"(a), "l"(b)); return d;
}

extern __shared__ float smem_dyn[];

__global__ __launch_bounds__(THREADS, 5)
void perlead_lstm_kernel(const float* __restrict__ x,
                         const float* __restrict__ W_ih,
                         const float* __restrict__ b_ih,
                         const float* __restrict__ b_hh,
                         const float* __restrict__ W_fc,
                         const float* __restrict__ b_fc,
                         float* __restrict__ y)
{
    // dynamic smem layout:
    //   sx2  : BT * ROW2 float2                  22016 B (x tile, y in place)
    //   sw   : LEADS * HP * 12 u64 (f32x2 pairs) 20160 B
    //   sbfc : LEADS float2                        336 B
    float2*     sx2  = reinterpret_cast<float2*>(smem_dyn);
    float*      swf  = smem_dyn + BT * ROW2 * 2;
    ulonglong2* swp  = reinterpret_cast<ulonglong2*>(swf);
    float2*     sbfc = reinterpret_cast<float2*>(swf + LEADS * HP * 24);

    const int tid  = threadIdx.x;
    const int lane = tid & 31;
    const int warp = tid >> 5;
    const long base2 = (long)blockIdx.x * (BT * LEADS);   // float2 units

    // ---- stage x tile (coalesced float2 global read) ----
    const float2* xg = reinterpret_cast<const float2*>(x) + base2;
    #pragma unroll 1
    for (int idx = tid; idx < BT * LEADS; idx += THREADS) {
        int bl = idx / LEADS;
        int j  = idx - bl * LEADS;
        sx2[bl * ROW2 + j] = xg[idx];
    }

    // ---- pack weights into shared, h-paired f32x2 layout ----
    // per (t,hp): 12 u64 slots, slot j = {v_j[h even], v_j[h odd]}
    // v = [.5wi0,.5wi1,.5bi, wg0,wg1,bg, .5wo0,.5wo1,.5bo, .25wf0,.25wf1, 0]
    for (int u = tid; u < LEADS * HID; u += THREADS) {
        int t = u / HID;
        int h = u - t * HID;
        const float* Wt = W_ih + (long)t * 40 * 2;
        float wi0 = Wt[(0 * HID + h) * 2 + 0];
        float wi1 = Wt[(0 * HID + h) * 2 + 1];
        float wg0 = Wt[(2 * HID + h) * 2 + 0];
        float wg1 = Wt[(2 * HID + h) * 2 + 1];
        float wo0 = Wt[(3 * HID + h) * 2 + 0];
        float wo1 = Wt[(3 * HID + h) * 2 + 1];
        float bi  = b_ih[t * 40 + 0 * HID + h] + b_hh[t * 40 + 0 * HID + h];
        float bg  = b_ih[t * 40 + 2 * HID + h] + b_hh[t * 40 + 2 * HID + h];
        float bo  = b_ih[t * 40 + 3 * HID + h] + b_hh[t * 40 + 3 * HID + h];
        float* d = swf + (t * HP + (h >> 1)) * 24 + (h & 1);
        d[0]  = 0.5f * wi0;   d[2]  = 0.5f * wi1;   d[4]  = 0.5f * bi;
        d[6]  = wg0;          d[8]  = wg1;          d[10] = bg;
        d[12] = 0.5f * wo0;   d[14] = 0.5f * wo1;   d[16] = 0.5f * bo;
        d[18] = 0.25f * W_fc[((long)t * 2 + 0) * HID + h];
        d[20] = 0.25f * W_fc[((long)t * 2 + 1) * HID + h];
        d[22] = 0.0f;
    }
    if (tid < LEADS) {
        sbfc[tid] = make_float2(b_fc[tid * 2 + 0], b_fc[tid * 2 + 1]);
    }

    __syncthreads();

    // packed poly constants (hoisted, 5 movs per thread total)
    const u64 C1  = pk(QC1, QC1);
    const u64 C2_ = pk(QC2, QC2);
    const u64 C3_ = pk(QC3, QC3);
    const u64 C4_ = pk(QC4, QC4);
    const u64 ONE2 = pk(1.0f, 1.0f);

    // ---- compute: warp-uniform t; f32x2 math over (h, h+1) pairs ----
    for (int t = warp; t < LEADS; t += NWARP) {
        float2 bfc = sbfc[t];
        u64 xx0[RG], xx1[RG], acc0[RG], acc1[RG];
        #pragma unroll
        for (int r = 0; r < RG; r++) {
            float2 xv = sx2[(r * 32 + lane) * ROW2 + t];
            xx0[r]  = pk(xv.x, xv.x);
            xx1[r]  = pk(xv.y, xv.y);
            acc0[r] = pk(bfc.x, 0.0f);
            acc1[r] = pk(bfc.y, 0.0f);
        }
        const ulonglong2* wt = swp + t * (HP * 6);
        #pragma unroll
        for (int hp = 0; hp < HP; hp++) {
            ulonglong2 w0 = wt[hp * 6 + 0];   // {wi0, wi1}
            ulonglong2 w1 = wt[hp * 6 + 1];   // {bi,  wg0}
            ulonglong2 w2 = wt[hp * 6 + 2];   // {wg1, bg }
            ulonglong2 w3 = wt[hp * 6 + 3];   // {wo0, wo1}
            ulonglong2 w4 = wt[hp * 6 + 4];   // {bo,  wf0}
            ulonglong2 w5 = wt[hp * 6 + 5];   // {wf1, pad}
            #pragma unroll
            for (int r = 0; r < RG; r++) {
                u64 iv = fma2(w0.x, xx0[r], fma2(w0.y, xx1[r], w1.x));  // i/2 pair
                u64 gv = fma2(w1.y, xx0[r], fma2(w2.x, xx1[r], w2.y));  // g pair
                u64 ov = fma2(w3.x, xx0[r], fma2(w3.y, xx1[r], w4.x));  // o/2 pair
                float i0, i1, g0, g1, o0, o1;
                upk(i0, i1, iv); upk(g0, g1, gv); upk(o0, o1, ov);
                u64 Ti = pk(tanh_approx(i0), tanh_approx(i1));
                u64 Tg = pk(tanh_approx(g0), tanh_approx(g1));
                u64 To = pk(tanh_approx(o0), tanh_approx(o1));
                u64 m  = fma2(Ti, Tg, Tg);                               // 2c pair
                u64 v  = mul2(m, m);
                u64 q  = fma2(fma2(fma2(C4_, v, C3_), v, C2_), v, C1);
                u64 Qv = fma2(v, q, ONE2);
                u64 s  = mul2(m, Qv);                                    // 2*tanh(c)
                u64 t2 = fma2(To, s, s);                                 // 4*h pair
                acc0[r] = fma2(w4.y, t2, acc0[r]);
                acc1[r] = fma2(w5.x, t2, acc1[r]);
            }
        }
        #pragma unroll
        for (int r = 0; r < RG; r++) {
            float a, b, c, d;
            upk(a, b, acc0[r]);
            upk(c, d, acc1[r]);
            sx2[(r * 32 + lane) * ROW2 + t] = make_float2(a + b, c + d);
        }
    }

    __syncthreads();

    // ---- write y tile (coalesced float2 global write) ----
    float2* yg = reinterpret_cast<float2*>(y) + base2;
    #pragma unroll 1
    for (int idx = tid; idx < BT * LEADS; idx += THREADS) {
        int bl = idx / LEADS;
        int j  = idx - bl * LEADS;
        yg[idx] = sx2[bl * ROW2 + j];
    }
}

extern "C" void kernel_launch(void* const* d_in, const int* in_sizes, int n_in,
                              void* d_out, int out_size) {
    const float* x    = (const float*)d_in[0];
    const float* W_ih = (const float*)d_in[1];
    const float* b_ih = (const float*)d_in[2];
    const float* b_hh = (const float*)d_in[3];
    const float* W_fc = (const float*)d_in[4];
    const float* b_fc = (const float*)d_in[5];
    float* y = (float*)d_out;

    const int smem_bytes = BT * ROW2 * 8 + LEADS * HP * 96 + LEADS * 8;
    static bool attr_set = false;
    if (!attr_set) {
        cudaFuncSetAttribute(perlead_lstm_kernel,
                             cudaFuncAttributeMaxDynamicSharedMemorySize, smem_bytes);
        attr_set = true;
    }

    int B = in_sizes[0] / (LEADS * 2);   // 131072
    int blocks = B / BT;                 // 2048
    perlead_lstm_kernel<<<blocks, THREADS, smem_bytes>>>(x, W_ih, b_ih, b_hh, W_fc, b_fc, y);
}